// round 1
// baseline (speedup 1.0000x reference)
#include <cuda_runtime.h>
#include <cstdint>

// Mandelbrot boundary-proximity loss.
//   iters(c): escape time with consecutive-step cycle detection (100 max)
//   out = 0.1 * mean(|iters - 30| / 30)
//
// Exact-integer reduction: iters in {1..100}, so sum(|iters-30|) is an exact
// integer (max ~5.9e8) -> deterministic ULL atomics, scalar finalized in double.

#define MAX_ITERS 100

__device__ unsigned long long g_sum;

__global__ void zero_kernel() { g_sum = 0ULL; }

__global__ void __launch_bounds__(256) mandel_kernel(
    const float* __restrict__ c_real,
    const float* __restrict__ c_imag,
    int n)
{
    const int idx = blockIdx.x * blockDim.x + threadIdx.x;

    unsigned int dist = 0;
    if (idx < n) {
        const float cr = c_real[idx];
        const float ci = c_imag[idx];

        float zr = 0.0f, zi = 0.0f;
        int iters = MAX_ITERS;  // default: never escaped / cycled -> 100

        #pragma unroll 4
        for (int i = 0; i < MAX_ITERS; ++i) {
            // z_new = z^2 + c
            float zr2 = zr * zr - zi * zi + cr;
            float zi2 = fmaf(2.0f * zr, zi, ci);

            // cycle detection vs previous z (skipped at i==0); takes
            // precedence over escape in the same step (matches reference
            // ordering: in_cycle clears active before just_escaped).
            if (i > 0) {
                float dr = fabsf(zr2 - zr);
                float di = fabsf(zi2 - zi);
                if (dr < 1e-6f && di < 1e-6f) { iters = MAX_ITERS; break; }
            }

            float mag = fmaf(zr2, zr2, zi2 * zi2);
            if (mag > 4.0f) { iters = i + 1; break; }

            zr = zr2; zi = zi2;
        }

        dist = (unsigned int)abs(iters - 30);
    }

    // warp reduce (int, exact)
    #pragma unroll
    for (int off = 16; off > 0; off >>= 1)
        dist += __shfl_down_sync(0xFFFFFFFFu, dist, off);

    // block reduce via shared, one atomic per block
    __shared__ unsigned int warp_sums[8];  // 256 threads / 32
    const int lane = threadIdx.x & 31;
    const int wid  = threadIdx.x >> 5;
    if (lane == 0) warp_sums[wid] = dist;
    __syncthreads();

    if (wid == 0) {
        unsigned int v = (lane < 8) ? warp_sums[lane] : 0u;
        #pragma unroll
        for (int off = 4; off > 0; off >>= 1)
            v += __shfl_down_sync(0xFFFFFFFFu, v, off);
        if (lane == 0)
            atomicAdd(&g_sum, (unsigned long long)v);
    }
}

__global__ void finalize_kernel(float* __restrict__ out, int n)
{
    // out = 0.1 * (sum / 30) / n
    double s = (double)g_sum;
    out[0] = (float)(s * (0.1 / 30.0) / (double)n);
}

extern "C" void kernel_launch(void* const* d_in, const int* in_sizes, int n_in,
                              void* d_out, int out_size)
{
    const float* c_real = (const float*)d_in[0];
    const float* c_imag = (const float*)d_in[1];
    float* out = (float*)d_out;
    const int n = in_sizes[0];

    zero_kernel<<<1, 1>>>();

    const int threads = 256;
    const int blocks = (n + threads - 1) / threads;
    mandel_kernel<<<blocks, threads>>>(c_real, c_imag, n);

    finalize_kernel<<<1, 1>>>(out, n);
}

// round 2
// speedup vs baseline: 2.3301x; 2.3301x over previous
#include <cuda_runtime.h>

// Mandelbrot boundary-proximity loss, two-phase with survivor compaction.
//
// Phase 1: all points, 12 iterations, escape check only. Escapees contribute
//          (30 - iters) to the exact-integer sum; survivors' indices are
//          compacted (block-aggregated append) into g_surv.
// Phase 2: persistent grid-stride over survivors; EXACT replay from iter 0
//          with the reference's cycle-detection semantics (cycle wins over
//          escape in the same step; i>0 gate). Arithmetic is bit-identical
//          to the R1 kernel (rel_err 1.9e-7), so phase boundaries are
//          consistent.
//
// Reduction: iters in {1..100} => sum(|iters-30|) is exact in ULL, so the
// result is deterministic (integer atomics, order-independent).

#define MAX_ITERS 100
#define K1 12
#define NMAX 8388608
#define P1_THREADS 512
#define P2_BLOCKS 2048
#define P2_THREADS 256

__device__ unsigned long long g_sum;
__device__ unsigned int g_nsurv;
__device__ unsigned int g_surv[NMAX];

__global__ void zero_kernel() { g_sum = 0ULL; g_nsurv = 0u; }

// ---------------------------------------------------------------- phase 1
__global__ void __launch_bounds__(P1_THREADS) phase1_kernel(
    const float* __restrict__ c_real,
    const float* __restrict__ c_imag,
    int n)
{
    const int idx  = blockIdx.x * P1_THREADS + threadIdx.x;
    const int lane = threadIdx.x & 31;
    const int wid  = threadIdx.x >> 5;

    unsigned int dist = 0;
    bool surv = false;

    if (idx < n) {
        const float cr = c_real[idx];
        const float ci = c_imag[idx];
        float zr = 0.0f, zi = 0.0f;
        int iters = 0;

        #pragma unroll
        for (int i = 0; i < K1; ++i) {
            float zr2 = zr * zr - zi * zi + cr;           // same expr as R1
            float zi2 = fmaf(2.0f * zr, zi, ci);
            if (fmaf(zr2, zr2, zi2 * zi2) > 4.0f) { iters = i + 1; break; }
            zr = zr2; zi = zi2;
        }

        if (iters) dist = (unsigned int)(30 - iters);      // iters in [1,12]
        else       surv = true;
    }

    // ---- block-aggregated survivor append (16 warps/block) ----
    __shared__ unsigned int warp_cnt[P1_THREADS / 32];
    __shared__ unsigned int block_base;

    const unsigned int mask = __ballot_sync(0xFFFFFFFFu, surv);
    if (lane == 0) warp_cnt[wid] = (unsigned int)__popc(mask);
    __syncthreads();

    if (threadIdx.x == 0) {
        unsigned int tot = 0;
        #pragma unroll
        for (int w = 0; w < P1_THREADS / 32; ++w) {
            unsigned int c = warp_cnt[w];
            warp_cnt[w] = tot;
            tot += c;
        }
        block_base = tot ? atomicAdd(&g_nsurv, tot) : 0u;
    }
    __syncthreads();

    if (surv) {
        unsigned int pos = block_base + warp_cnt[wid]
                         + (unsigned int)__popc(mask & ((1u << lane) - 1u));
        g_surv[pos] = (unsigned int)idx;
    }

    // ---- exact-integer distance reduction ----
    #pragma unroll
    for (int off = 16; off > 0; off >>= 1)
        dist += __shfl_down_sync(0xFFFFFFFFu, dist, off);

    __shared__ unsigned int warp_sums[P1_THREADS / 32];
    if (lane == 0) warp_sums[wid] = dist;
    __syncthreads();

    if (wid == 0) {
        unsigned int v = (lane < P1_THREADS / 32) ? warp_sums[lane] : 0u;
        #pragma unroll
        for (int off = 8; off > 0; off >>= 1)
            v += __shfl_down_sync(0xFFFFFFFFu, v, off);
        if (lane == 0 && v)
            atomicAdd(&g_sum, (unsigned long long)v);
    }
}

// ---------------------------------------------------------------- phase 2
__global__ void __launch_bounds__(P2_THREADS) phase2_kernel(
    const float* __restrict__ c_real,
    const float* __restrict__ c_imag)
{
    const unsigned int total  = g_nsurv;
    const unsigned int stride = gridDim.x * blockDim.x;

    unsigned int local = 0;

    for (unsigned int s = blockIdx.x * blockDim.x + threadIdx.x;
         s < total; s += stride) {
        const unsigned int idx = g_surv[s];
        const float cr = __ldg(c_real + idx);
        const float ci = __ldg(c_imag + idx);

        float zr = 0.0f, zi = 0.0f;
        int iters = MAX_ITERS;   // never escaped / cycled -> 100

        for (int i = 0; i < MAX_ITERS; ++i) {
            float zr2 = zr * zr - zi * zi + cr;            // same expr as R1
            float zi2 = fmaf(2.0f * zr, zi, ci);

            // cycle detection (skipped at i==0); wins over escape same-step
            if (i > 0) {
                float dr = fabsf(zr2 - zr);
                float di = fabsf(zi2 - zi);
                if (dr < 1e-6f && di < 1e-6f) { iters = MAX_ITERS; break; }
            }

            if (fmaf(zr2, zr2, zi2 * zi2) > 4.0f) { iters = i + 1; break; }

            zr = zr2; zi = zi2;
        }

        local += (unsigned int)abs(iters - 30);
    }

    // ---- reduction ----
    #pragma unroll
    for (int off = 16; off > 0; off >>= 1)
        local += __shfl_down_sync(0xFFFFFFFFu, local, off);

    __shared__ unsigned int warp_sums[P2_THREADS / 32];
    const int lane = threadIdx.x & 31;
    const int wid  = threadIdx.x >> 5;
    if (lane == 0) warp_sums[wid] = local;
    __syncthreads();

    if (wid == 0) {
        unsigned int v = (lane < P2_THREADS / 32) ? warp_sums[lane] : 0u;
        #pragma unroll
        for (int off = 4; off > 0; off >>= 1)
            v += __shfl_down_sync(0xFFFFFFFFu, v, off);
        if (lane == 0 && v)
            atomicAdd(&g_sum, (unsigned long long)v);
    }
}

// ---------------------------------------------------------------- finalize
__global__ void finalize_kernel(float* __restrict__ out, int n)
{
    double s = (double)g_sum;
    out[0] = (float)(s * (0.1 / 30.0) / (double)n);
}

extern "C" void kernel_launch(void* const* d_in, const int* in_sizes, int n_in,
                              void* d_out, int out_size)
{
    const float* c_real = (const float*)d_in[0];
    const float* c_imag = (const float*)d_in[1];
    float* out = (float*)d_out;
    const int n = in_sizes[0];

    zero_kernel<<<1, 1>>>();

    const int p1_blocks = (n + P1_THREADS - 1) / P1_THREADS;
    phase1_kernel<<<p1_blocks, P1_THREADS>>>(c_real, c_imag, n);

    phase2_kernel<<<P2_BLOCKS, P2_THREADS>>>(c_real, c_imag);

    finalize_kernel<<<1, 1>>>(out, n);
}

// round 3
// speedup vs baseline: 4.3318x; 1.8591x over previous
#include <cuda_runtime.h>

// Mandelbrot boundary-proximity loss, two-phase + analytic in-set filter.
//
// Key semantics: any point that never escapes within 100 iters ends at
// iters=100 (via cycle detection -> max_f, or loop exhaustion -> 100).
// Points inside the main cardioid or the period-2 bulb provably never
// escape => dist = |100-30| = 70 with zero iteration work.
//
// Phase 1: classify cardioid/bulb (dist=70); else iterate 12 escape-only
//          steps; escapees contribute (30-iters); rest -> survivor list.
// Phase 2: exact replay from iter 0 with reference cycle semantics
//          (bit-identical arithmetic to the R1 kernel, rel_err 1.9e-7).
//
// Reduction is an exact integer sum (ULL atomics) => deterministic.
// No zero kernel: device globals are zero-init at load; finalize resets
// them after reading, so every graph replay starts from identical state.

#define MAX_ITERS 100
#define K1 12
#define NMAX 8388608
#define P1_THREADS 512
#define P2_BLOCKS 2048
#define P2_THREADS 256

__device__ unsigned long long g_sum;      // zero-init
__device__ unsigned int g_nsurv;          // zero-init
__device__ unsigned int g_surv[NMAX];

// ---------------------------------------------------------------- phase 1
__global__ void __launch_bounds__(P1_THREADS) phase1_kernel(
    const float* __restrict__ c_real,
    const float* __restrict__ c_imag,
    int n)
{
    const int idx  = blockIdx.x * P1_THREADS + threadIdx.x;
    const int lane = threadIdx.x & 31;
    const int wid  = threadIdx.x >> 5;

    unsigned int dist = 0;
    bool surv = false;

    if (idx < n) {
        const float cr = c_real[idx];
        const float ci = c_imag[idx];

        // analytic in-set tests (main cardioid + period-2 bulb)
        const float ci2 = ci * ci;
        const float xm  = cr - 0.25f;
        const float q   = xm * xm + ci2;
        const float xp  = cr + 1.0f;
        const bool in_card = q * (q + xm) < 0.25f * ci2;
        const bool in_bulb = xp * xp + ci2 < 0.0625f;

        if (in_card || in_bulb) {
            dist = 70u;                       // iters = 100 exactly
        } else {
            float zr = 0.0f, zi = 0.0f;
            int iters = 0;

            #pragma unroll
            for (int i = 0; i < K1; ++i) {
                float zr2 = zr * zr - zi * zi + cr;       // same expr as R1
                float zi2 = fmaf(2.0f * zr, zi, ci);
                if (fmaf(zr2, zr2, zi2 * zi2) > 4.0f) { iters = i + 1; break; }
                zr = zr2; zi = zi2;
            }

            if (iters) dist = (unsigned int)(30 - iters); // iters in [1,12]
            else       surv = true;
        }
    }

    // ---- block-aggregated survivor append ----
    __shared__ unsigned int warp_cnt[P1_THREADS / 32];
    __shared__ unsigned int block_base;

    const unsigned int mask = __ballot_sync(0xFFFFFFFFu, surv);
    if (lane == 0) warp_cnt[wid] = (unsigned int)__popc(mask);
    __syncthreads();

    if (threadIdx.x == 0) {
        unsigned int tot = 0;
        #pragma unroll
        for (int w = 0; w < P1_THREADS / 32; ++w) {
            unsigned int c = warp_cnt[w];
            warp_cnt[w] = tot;
            tot += c;
        }
        block_base = tot ? atomicAdd(&g_nsurv, tot) : 0u;
    }
    __syncthreads();

    if (surv) {
        unsigned int pos = block_base + warp_cnt[wid]
                         + (unsigned int)__popc(mask & ((1u << lane) - 1u));
        g_surv[pos] = (unsigned int)idx;
    }

    // ---- exact-integer distance reduction ----
    #pragma unroll
    for (int off = 16; off > 0; off >>= 1)
        dist += __shfl_down_sync(0xFFFFFFFFu, dist, off);

    __shared__ unsigned int warp_sums[P1_THREADS / 32];
    if (lane == 0) warp_sums[wid] = dist;
    __syncthreads();

    if (wid == 0) {
        unsigned int v = (lane < P1_THREADS / 32) ? warp_sums[lane] : 0u;
        #pragma unroll
        for (int off = 8; off > 0; off >>= 1)
            v += __shfl_down_sync(0xFFFFFFFFu, v, off);
        if (lane == 0 && v)
            atomicAdd(&g_sum, (unsigned long long)v);
    }
}

// ---------------------------------------------------------------- phase 2
__global__ void __launch_bounds__(P2_THREADS) phase2_kernel(
    const float* __restrict__ c_real,
    const float* __restrict__ c_imag)
{
    const unsigned int total  = g_nsurv;
    const unsigned int stride = gridDim.x * blockDim.x;

    unsigned int local = 0;

    for (unsigned int s = blockIdx.x * blockDim.x + threadIdx.x;
         s < total; s += stride) {
        const unsigned int idx = g_surv[s];
        const float cr = __ldg(c_real + idx);
        const float ci = __ldg(c_imag + idx);

        float zr = 0.0f, zi = 0.0f;
        int iters = MAX_ITERS;   // never escaped / cycled -> 100

        for (int i = 0; i < MAX_ITERS; ++i) {
            float zr2 = zr * zr - zi * zi + cr;            // same expr as R1
            float zi2 = fmaf(2.0f * zr, zi, ci);

            // cycle detection (skipped at i==0); wins over escape same-step
            if (i > 0) {
                float dr = fabsf(zr2 - zr);
                float di = fabsf(zi2 - zi);
                if (dr < 1e-6f && di < 1e-6f) { iters = MAX_ITERS; break; }
            }

            if (fmaf(zr2, zr2, zi2 * zi2) > 4.0f) { iters = i + 1; break; }

            zr = zr2; zi = zi2;
        }

        local += (unsigned int)abs(iters - 30);
    }

    // ---- reduction ----
    #pragma unroll
    for (int off = 16; off > 0; off >>= 1)
        local += __shfl_down_sync(0xFFFFFFFFu, local, off);

    __shared__ unsigned int warp_sums[P2_THREADS / 32];
    const int lane = threadIdx.x & 31;
    const int wid  = threadIdx.x >> 5;
    if (lane == 0) warp_sums[wid] = local;
    __syncthreads();

    if (wid == 0) {
        unsigned int v = (lane < P2_THREADS / 32) ? warp_sums[lane] : 0u;
        #pragma unroll
        for (int off = 4; off > 0; off >>= 1)
            v += __shfl_down_sync(0xFFFFFFFFu, v, off);
        if (lane == 0 && v)
            atomicAdd(&g_sum, (unsigned long long)v);
    }
}

// ---------------------------------------------------------------- finalize
__global__ void finalize_kernel(float* __restrict__ out, int n)
{
    double s = (double)g_sum;
    out[0] = (float)(s * (0.1 / 30.0) / (double)n);
    // reset for next graph replay (identical state each call => deterministic)
    g_sum = 0ULL;
    g_nsurv = 0u;
}

extern "C" void kernel_launch(void* const* d_in, const int* in_sizes, int n_in,
                              void* d_out, int out_size)
{
    const float* c_real = (const float*)d_in[0];
    const float* c_imag = (const float*)d_in[1];
    float* out = (float*)d_out;
    const int n = in_sizes[0];

    const int p1_blocks = (n + P1_THREADS - 1) / P1_THREADS;
    phase1_kernel<<<p1_blocks, P1_THREADS>>>(c_real, c_imag, n);

    phase2_kernel<<<P2_BLOCKS, P2_THREADS>>>(c_real, c_imag);

    finalize_kernel<<<1, 1>>>(out, n);
}